// round 4
// baseline (speedup 1.0000x reference)
#include <cuda_runtime.h>
#include <math.h>
#include <stdint.h>

#define BATCH  4
#define LSEQ   4096
#define DMODEL 1024
#define DINNER 2048
#define DTR    64
#define NST    16
#define XDBLC  96   // dt_rank + 2*N

// ---------------- scratch (device globals) ----------------
__device__ float g_xr  [(size_t)BATCH * LSEQ * (2 * DINNER)];  // in-proj out (x | res)
__device__ float g_xc  [(size_t)BATCH * LSEQ * DINNER];        // conv+silu -> y(gated) in place
__device__ float g_xdbl[(size_t)BATCH * LSEQ * XDBLC];
__device__ float g_dt  [(size_t)BATCH * LSEQ * DINNER];

// ---------------- tf32 tensor-core GEMM (2xTF32, A pre-split in smem) ------
#define BM 128
#define BN 128
#define BKK 32
#define ALD 44    // (BKK + 12): 176B rows, 16B aligned, conflict-free frag loads
#define BLD 132   // (BN + 4)
#define SMEM_GEMM ((2 * BM * ALD + BKK * BLD) * 4)   // 61952 bytes -> 2 blocks/SM

__device__ __forceinline__ uint32_t f2tf(float f) {
    uint32_t r; asm("cvt.rna.tf32.f32 %0, %1;" : "=r"(r) : "f"(f)); return r;
}

__device__ __forceinline__ void mma8(float* c,
    uint32_t a0, uint32_t a1, uint32_t a2, uint32_t a3, uint32_t b0, uint32_t b1)
{
    asm volatile(
        "mma.sync.aligned.m16n8k8.row.col.f32.tf32.tf32.f32 "
        "{%0,%1,%2,%3}, {%4,%5,%6,%7}, {%8,%9}, {%0,%1,%2,%3};"
        : "+f"(c[0]), "+f"(c[1]), "+f"(c[2]), "+f"(c[3])
        : "r"(a0), "r"(a1), "r"(a2), "r"(a3), "r"(b0), "r"(b1));
}

// C[M,N] = A[M,K] @ B[K,N] (+bias) (+softplus if epi==1)
// M % 128 == 0, K % 32 == 0; N arbitrary (guarded).
__global__ __launch_bounds__(256, 2)
void mma_gemm(const float* __restrict__ A, const float* __restrict__ B,
              const float* __restrict__ bias, float* __restrict__ C,
              int M, int N, int K, int lda, int ldb, int ldc, int epi)
{
    extern __shared__ float smem[];
    float (*Ah)[ALD] = (float(*)[ALD])smem;                 // tf32 hi of A
    float (*Al)[ALD] = (float(*)[ALD])(smem + BM * ALD);    // tf32 lo of A
    float (*Bs)[BLD] = (float(*)[BLD])(smem + 2 * BM * ALD);// tf32 B

    const int tid = threadIdx.x;
    const int bm = blockIdx.y * BM;
    const int bn = blockIdx.x * BN;

    const int wid = tid >> 5, lane = tid & 31;
    const int wm = wid >> 1, wn = wid & 1;         // 4 x 2 warps; warp tile 32x64
    const int qr = lane >> 2, qc = lane & 3;

    float acc[2][8][4];
    #pragma unroll
    for (int i = 0; i < 2; i++)
        #pragma unroll
        for (int j = 0; j < 8; j++)
            #pragma unroll
            for (int e = 0; e < 4; e++) acc[i][j][e] = 0.f;

    for (int kt = 0; kt < K; kt += BKK) {
        // ---- load (batched LDGs), convert, store to smem ----
        float4 ra[4], rb[4];
        #pragma unroll
        for (int t = 0; t < 4; t++) {
            const int f4 = tid + t * 256;
            const int r = f4 >> 3, c = (f4 & 7) * 4;
            ra[t] = *(const float4*)(A + (size_t)(bm + r) * lda + kt + c);
            const int k = f4 >> 5, cb = (f4 & 31) * 4;
            const int n = bn + cb;
            const float* p = B + (size_t)(kt + k) * ldb + n;
            if (n + 3 < N) {
                rb[t] = *(const float4*)p;
            } else {
                float4 v;
                v.x = (n + 0 < N) ? p[0] : 0.f;
                v.y = (n + 1 < N) ? p[1] : 0.f;
                v.z = (n + 2 < N) ? p[2] : 0.f;
                v.w = (n + 3 < N) ? p[3] : 0.f;
                rb[t] = v;
            }
        }
        #pragma unroll
        for (int t = 0; t < 4; t++) {
            const int f4 = tid + t * 256;
            const int r = f4 >> 3, c = (f4 & 7) * 4;
            float4 hi, lo;
            hi.x = __uint_as_float(f2tf(ra[t].x)); lo.x = __uint_as_float(f2tf(ra[t].x - hi.x));
            hi.y = __uint_as_float(f2tf(ra[t].y)); lo.y = __uint_as_float(f2tf(ra[t].y - hi.y));
            hi.z = __uint_as_float(f2tf(ra[t].z)); lo.z = __uint_as_float(f2tf(ra[t].z - hi.z));
            hi.w = __uint_as_float(f2tf(ra[t].w)); lo.w = __uint_as_float(f2tf(ra[t].w - hi.w));
            *(float4*)&Ah[r][c] = hi;
            *(float4*)&Al[r][c] = lo;
            const int k = f4 >> 5, cb = (f4 & 31) * 4;
            float4 bv;
            bv.x = __uint_as_float(f2tf(rb[t].x));
            bv.y = __uint_as_float(f2tf(rb[t].y));
            bv.z = __uint_as_float(f2tf(rb[t].z));
            bv.w = __uint_as_float(f2tf(rb[t].w));
            *(float4*)&Bs[k][cb] = bv;
        }
        __syncthreads();

        // ---- compute ----
        #pragma unroll
        for (int kk = 0; kk < BKK; kk += 8) {
            uint32_t ah[2][4], al[2][4];
            #pragma unroll
            for (int tm = 0; tm < 2; tm++) {
                const int r0 = wm * 32 + tm * 16 + qr;
                ah[tm][0] = __float_as_uint(Ah[r0    ][kk + qc]);
                ah[tm][1] = __float_as_uint(Ah[r0 + 8][kk + qc]);
                ah[tm][2] = __float_as_uint(Ah[r0    ][kk + qc + 4]);
                ah[tm][3] = __float_as_uint(Ah[r0 + 8][kk + qc + 4]);
                al[tm][0] = __float_as_uint(Al[r0    ][kk + qc]);
                al[tm][1] = __float_as_uint(Al[r0 + 8][kk + qc]);
                al[tm][2] = __float_as_uint(Al[r0    ][kk + qc + 4]);
                al[tm][3] = __float_as_uint(Al[r0 + 8][kk + qc + 4]);
            }
            #pragma unroll
            for (int tn = 0; tn < 8; tn++) {
                const int col = wn * 64 + tn * 8 + qr;
                const uint32_t b0 = __float_as_uint(Bs[kk + qc][col]);
                const uint32_t b1 = __float_as_uint(Bs[kk + qc + 4][col]);
                #pragma unroll
                for (int tm = 0; tm < 2; tm++) {
                    mma8(acc[tm][tn], al[tm][0], al[tm][1], al[tm][2], al[tm][3], b0, b1);
                    mma8(acc[tm][tn], ah[tm][0], ah[tm][1], ah[tm][2], ah[tm][3], b0, b1);
                }
            }
        }
        __syncthreads();
    }

    // ---- epilogue ----
    #pragma unroll
    for (int tm = 0; tm < 2; tm++) {
        const int r0 = bm + wm * 32 + tm * 16 + qr;
        #pragma unroll
        for (int tn = 0; tn < 8; tn++) {
            const int c0 = bn + wn * 64 + tn * 8 + 2 * qc;
            #pragma unroll
            for (int half = 0; half < 2; half++) {
                const int r = r0 + half * 8;
                float v0 = acc[tm][tn][half * 2 + 0];
                float v1 = acc[tm][tn][half * 2 + 1];
                if (bias && c0 < N) { v0 += bias[c0]; if (c0 + 1 < N) v1 += bias[c0 + 1]; }
                if (epi == 1) {
                    v0 = (v0 > 20.f) ? v0 : log1pf(expf(v0));
                    v1 = (v1 > 20.f) ? v1 : log1pf(expf(v1));
                }
                if (c0 + 1 < N) {
                    *(float2*)(C + (size_t)r * ldc + c0) = make_float2(v0, v1);
                } else if (c0 < N) {
                    C[(size_t)r * ldc + c0] = v0;
                }
            }
        }
    }
}

// ---------------- causal depthwise conv (K=4) + SiLU, float4 along d ------
__global__ __launch_bounds__(256)
void conv_silu_kernel(const float* __restrict__ conv_w, const float* __restrict__ conv_b)
{
    const size_t total4 = (size_t)BATCH * LSEQ * (DINNER / 4);
    size_t idx = (size_t)blockIdx.x * blockDim.x + threadIdx.x;
    if (idx >= total4) return;
    const int d4 = (int)(idx % (DINNER / 4));
    const int l  = (int)((idx / (DINNER / 4)) % LSEQ);
    const int b  = (int)(idx / ((size_t)(DINNER / 4) * LSEQ));
    const int d  = d4 * 4;

    float acc0 = conv_b[d], acc1 = conv_b[d + 1], acc2 = conv_b[d + 2], acc3 = conv_b[d + 3];
    #pragma unroll
    for (int k = 0; k < 4; k++) {
        const int ls = l - 3 + k;
        if (ls >= 0) {
            const float4 v = *(const float4*)(&g_xr[((size_t)b * LSEQ + ls) * (2 * DINNER) + d]);
            acc0 = fmaf(conv_w[(d + 0) * 4 + k], v.x, acc0);
            acc1 = fmaf(conv_w[(d + 1) * 4 + k], v.y, acc1);
            acc2 = fmaf(conv_w[(d + 2) * 4 + k], v.z, acc2);
            acc3 = fmaf(conv_w[(d + 3) * 4 + k], v.w, acc3);
        }
    }
    float4 o;
    o.x = acc0 / (1.f + __expf(-acc0));
    o.y = acc1 / (1.f + __expf(-acc1));
    o.z = acc2 / (1.f + __expf(-acc2));
    o.w = acc3 / (1.f + __expf(-acc3));
    *(float4*)(&g_xc[((size_t)b * LSEQ + l) * DINNER + d]) = o;
}

// ---------------- selective scan over L (+x*D, fused gate) --------------
#define SCAN_T 128
__global__ __launch_bounds__(64)
void scan_kernel(const float* __restrict__ A_log, const float* __restrict__ D_par)
{
    __shared__ float sBC[SCAN_T][32];

    const int tid = threadIdx.x;
    const int d = blockIdx.x * 64 + tid;   // 0..2047
    const int b = blockIdx.y;

    float A[NST];
    #pragma unroll
    for (int n = 0; n < NST; n++) A[n] = -expf(A_log[d * NST + n]);
    float h[NST];
    #pragma unroll
    for (int n = 0; n < NST; n++) h[n] = 0.f;
    const float Dp = D_par[d];

    size_t pd = (size_t)b * LSEQ * DINNER + d;
    size_t pr = (size_t)b * LSEQ * (2 * DINNER) + DINNER + d;

    float dt_nx = g_dt[pd];
    float xt_nx = g_xc[pd];
    float rr_nx = g_xr[pr];

    const float* xdb = g_xdbl + (size_t)b * LSEQ * XDBLC + DTR;

    for (int c = 0; c < LSEQ / SCAN_T; c++) {
        __syncthreads();
        const float* src = xdb + (size_t)c * SCAN_T * XDBLC;
        #pragma unroll 4
        for (int i = tid; i < SCAN_T * 8; i += 64) {
            const int row = i >> 3, c4 = (i & 7) * 4;
            *(float4*)&sBC[row][c4] = *(const float4*)(src + (size_t)row * XDBLC + c4);
        }
        __syncthreads();

        for (int t = 0; t < SCAN_T; t++) {
            const float dt = dt_nx, xt = xt_nx, rr = rr_nx;
            const size_t pd_cur = pd;
            const int l = c * SCAN_T + t;
            pd += DINNER; pr += 2 * DINNER;
            if (l + 1 < LSEQ) {
                dt_nx = g_dt[pd];
                xt_nx = g_xc[pd];
                rr_nx = g_xr[pr];
            }

            const float dtx = dt * xt;
            float yt = 0.f;
            #pragma unroll
            for (int n = 0; n < NST; n++) {
                const float dA = __expf(dt * A[n]);
                h[n] = fmaf(h[n], dA, dtx * sBC[t][n]);
                yt   = fmaf(h[n], sBC[t][NST + n], yt);
            }
            const float gate = rr / (1.f + __expf(-rr));
            g_xc[pd_cur] = fmaf(xt, Dp, yt) * gate;
        }
    }
}

// ---------------- launch -------------------------------------------------
extern "C" void kernel_launch(void* const* d_in, const int* in_sizes, int n_in,
                              void* d_out, int out_size)
{
    const float* x      = (const float*)d_in[0];
    const float* W_in   = (const float*)d_in[1];
    const float* b_in   = (const float*)d_in[2];
    const float* conv_w = (const float*)d_in[3];
    const float* conv_b = (const float*)d_in[4];
    const float* W_x    = (const float*)d_in[5];
    const float* W_dt   = (const float*)d_in[6];
    const float* b_dt   = (const float*)d_in[7];
    const float* A_log  = (const float*)d_in[8];
    const float* D_par  = (const float*)d_in[9];
    const float* W_out  = (const float*)d_in[10];
    const float* b_out  = (const float*)d_in[11];
    float* out = (float*)d_out;

    float *xr, *xc, *xdbl, *dt;
    cudaGetSymbolAddress((void**)&xr,   g_xr);
    cudaGetSymbolAddress((void**)&xc,   g_xc);
    cudaGetSymbolAddress((void**)&xdbl, g_xdbl);
    cudaGetSymbolAddress((void**)&dt,   g_dt);

    cudaFuncSetAttribute(mma_gemm, cudaFuncAttributeMaxDynamicSharedMemorySize, SMEM_GEMM);

    const int M = BATCH * LSEQ;   // 16384

    // 1) in-projection: [M,1024] @ [1024,4096] -> g_xr
    mma_gemm<<<dim3((2 * DINNER) / BN, M / BM), 256, SMEM_GEMM>>>(
        x, W_in, b_in, xr, M, 2 * DINNER, DMODEL, DMODEL, 2 * DINNER, 2 * DINNER, 0);

    // 2) causal depthwise conv + silu -> g_xc
    {
        const size_t total4 = (size_t)M * (DINNER / 4);
        conv_silu_kernel<<<(unsigned)((total4 + 255) / 256), 256>>>(conv_w, conv_b);
    }

    // 3) x_dbl: [M,2048] @ [2048,96] -> g_xdbl
    mma_gemm<<<dim3(1, M / BM), 256, SMEM_GEMM>>>(
        xc, W_x, nullptr, xdbl, M, XDBLC, DINNER, DINNER, XDBLC, XDBLC, 0);

    // 4) delta: softplus([M,64] @ [64,2048] + b_dt) -> g_dt
    mma_gemm<<<dim3(DINNER / BN, M / BM), 256, SMEM_GEMM>>>(
        xdbl, W_dt, b_dt, dt, M, DINNER, DTR, XDBLC, DINNER, DINNER, 1);

    // 5) selective scan (y in place over g_xc, + x*D, * silu(res))
    scan_kernel<<<dim3(DINNER / 64, BATCH), 64>>>(A_log, D_par);

    // 6) out-projection: [M,2048] @ [2048,1024] + b_out -> d_out
    mma_gemm<<<dim3(DMODEL / BN, M / BM), 256, SMEM_GEMM>>>(
        xc, W_out, b_out, out, M, DMODEL, DINNER, DINNER, DMODEL, DMODEL, 0);
}

// round 8
// speedup vs baseline: 1.0990x; 1.0990x over previous
#include <cuda_runtime.h>
#include <math.h>
#include <stdint.h>

#define BATCH  4
#define LSEQ   4096
#define DMODEL 1024
#define DINNER 2048
#define DTR    64
#define NST    16
#define XDBLC  96   // dt_rank + 2*N

// ---------------- scratch (device globals) ----------------
__device__ float g_xr  [(size_t)BATCH * LSEQ * (2 * DINNER)];  // in-proj out (x | res)
__device__ float g_xc  [(size_t)BATCH * LSEQ * DINNER];        // conv+silu -> y(gated) in place
__device__ float g_xdbl[(size_t)BATCH * LSEQ * XDBLC];
__device__ float g_dt  [(size_t)BATCH * LSEQ * DINNER];

// ---------------- helpers ----------------
__device__ __forceinline__ uint32_t smem_u32(const void* p) {
    uint32_t a;
    asm("{ .reg .u64 t; cvta.to.shared.u64 t, %1; cvt.u32.u64 %0, t; }" : "=r"(a) : "l"(p));
    return a;
}
__device__ __forceinline__ uint32_t f2tf(float f) {
    uint32_t r; asm("cvt.rna.tf32.f32 %0, %1;" : "=r"(r) : "f"(f)); return r;
}
__device__ __forceinline__ void cp16(uint32_t dst, const void* src, uint32_t sz) {
    asm volatile("cp.async.cg.shared.global [%0], [%1], 16, %2;"
                 :: "r"(dst), "l"(src), "r"(sz) : "memory");
}
__device__ __forceinline__ void mma8(float* c,
    uint32_t a0, uint32_t a1, uint32_t a2, uint32_t a3, uint32_t b0, uint32_t b1)
{
    asm volatile(
        "mma.sync.aligned.m16n8k8.row.col.f32.tf32.tf32.f32 "
        "{%0,%1,%2,%3}, {%4,%5,%6,%7}, {%8,%9}, {%0,%1,%2,%3};"
        : "+f"(c[0]), "+f"(c[1]), "+f"(c[2]), "+f"(c[3])
        : "r"(a0), "r"(a1), "r"(a2), "r"(a3), "r"(b0), "r"(b1));
}

// ---------------- smem layout (bytes) ----------------
// staging A (raw fp32 == tf32-hi via HW truncation): [128][36] x2 stages
// staging B (raw fp32): [32][128] x2 stages
// conv A-lo: [128][36] ; conv B (rna tf32): [32][136]
#define STG_A0 0
#define STG_A1 18432
#define STG_B0 36864
#define STG_B1 53248
#define OFF_AL 69632
#define OFF_BS 88064
#define SMEM_GEMM 105472

// C[M,N] = A[M,K] @ B[K,N] (+bias)(+softplus if epi==1)
// M % 128 == 0, K % 32 == 0; N arbitrary mult of 4 (zero-filled / guarded).
__global__ __launch_bounds__(256, 2)
void mma_gemm(const float* __restrict__ A, const float* __restrict__ B,
              const float* __restrict__ bias, float* __restrict__ C,
              int M, int N, int K, int lda, int ldb, int ldc, int epi)
{
    extern __shared__ char smc[];
    const uint32_t sb = smem_u32(smc);
    const int tid = threadIdx.x;
    const int bm = blockIdx.y * 128;
    const int bn = blockIdx.x * 128;
    const int wid = tid >> 5, lane = tid & 31;
    const int wm = wid >> 1, wn = wid & 1;     // 4x2 warps, warp tile 32x64
    const int qr = lane >> 2, qc = lane & 3;

    float acc[2][8][4];
    #pragma unroll
    for (int i = 0; i < 2; i++)
        #pragma unroll
        for (int j = 0; j < 8; j++)
            #pragma unroll
            for (int e = 0; e < 4; e++) acc[i][j][e] = 0.f;

    const int rA = tid >> 3, cA = (tid & 7) * 4;     // A loader: +32 rows per t
    const int kB = tid >> 5, nB = (tid & 31) * 4;    // B loader: +8 rows per t
    const uint32_t bsz = (bn + nB < N) ? 16u : 0u;
    const int nclamp = (bn + nB < N) ? (bn + nB) : 0; // safe addr when sz=0

    auto issue = [&](int ch) {
        const int kt = ch << 5;
        const int st = ch & 1;
        const uint32_t dA = sb + (st ? STG_A1 : STG_A0);
        const uint32_t dB = sb + (st ? STG_B1 : STG_B0);
        #pragma unroll
        for (int t = 0; t < 4; t++) {
            const int r = rA + t * 32;
            cp16(dA + (uint32_t)(r * 36 + cA) * 4,
                 A + (size_t)(bm + r) * lda + kt + cA, 16u);
            const int k = kB + t * 8;
            cp16(dB + (uint32_t)(k * 128 + nB) * 4,
                 B + (size_t)(kt + k) * ldb + nclamp, bsz);
        }
        asm volatile("cp.async.commit_group;" ::: "memory");
    };

    issue(0);
    const int nch = K >> 5;

    for (int i = 0; i < nch; i++) {
        asm volatile("cp.async.wait_group 0;" ::: "memory");
        __syncthreads();                       // stage i visible; prev compute done
        if (i + 1 < nch) issue(i + 1);

        // ---- convert: A-lo (residual of HW tf32 truncation) + B (rna tf32) ----
        const int st = i & 1;
        const char* srcA = smc + (st ? STG_A1 : STG_A0);
        const char* srcB = smc + (st ? STG_B1 : STG_B0);
        #pragma unroll
        for (int t = 0; t < 4; t++) {
            const int r = rA + t * 32;
            const float4 a = *(const float4*)(srcA + (uint32_t)(r * 36 + cA) * 4);
            float4 lo;
            lo.x = __uint_as_float(f2tf(a.x - __uint_as_float(__float_as_uint(a.x) & 0xFFFFE000u)));
            lo.y = __uint_as_float(f2tf(a.y - __uint_as_float(__float_as_uint(a.y) & 0xFFFFE000u)));
            lo.z = __uint_as_float(f2tf(a.z - __uint_as_float(__float_as_uint(a.z) & 0xFFFFE000u)));
            lo.w = __uint_as_float(f2tf(a.w - __uint_as_float(__float_as_uint(a.w) & 0xFFFFE000u)));
            *(float4*)(smc + OFF_AL + (uint32_t)(r * 36 + cA) * 4) = lo;

            const int k = kB + t * 8;
            const float4 b = *(const float4*)(srcB + (uint32_t)(k * 128 + nB) * 4);
            float4 bt;
            bt.x = __uint_as_float(f2tf(b.x));
            bt.y = __uint_as_float(f2tf(b.y));
            bt.z = __uint_as_float(f2tf(b.z));
            bt.w = __uint_as_float(f2tf(b.w));
            *(float4*)(smc + OFF_BS + (uint32_t)(k * 136 + nB) * 4) = bt;
        }
        __syncthreads();

        // ---- compute ----
        const uint32_t* Ahi = (const uint32_t*)srcA;
        const uint32_t* Alo = (const uint32_t*)(smc + OFF_AL);
        const uint32_t* Bsm = (const uint32_t*)(smc + OFF_BS);
        #pragma unroll
        for (int kk = 0; kk < 32; kk += 8) {
            uint32_t ah[2][4], al[2][4];
            #pragma unroll
            for (int tm = 0; tm < 2; tm++) {
                const int r0 = wm * 32 + tm * 16 + qr;
                ah[tm][0] = Ahi[r0 * 36 + kk + qc];
                ah[tm][1] = Ahi[(r0 + 8) * 36 + kk + qc];
                ah[tm][2] = Ahi[r0 * 36 + kk + qc + 4];
                ah[tm][3] = Ahi[(r0 + 8) * 36 + kk + qc + 4];
                al[tm][0] = Alo[r0 * 36 + kk + qc];
                al[tm][1] = Alo[(r0 + 8) * 36 + kk + qc];
                al[tm][2] = Alo[r0 * 36 + kk + qc + 4];
                al[tm][3] = Alo[(r0 + 8) * 36 + kk + qc + 4];
            }
            #pragma unroll
            for (int tn = 0; tn < 8; tn++) {
                const int col = wn * 64 + tn * 8 + qr;
                const uint32_t b0 = Bsm[(kk + qc) * 136 + col];
                const uint32_t b1 = Bsm[(kk + qc + 4) * 136 + col];
                #pragma unroll
                for (int tm = 0; tm < 2; tm++) {
                    mma8(acc[tm][tn], al[tm][0], al[tm][1], al[tm][2], al[tm][3], b0, b1);
                    mma8(acc[tm][tn], ah[tm][0], ah[tm][1], ah[tm][2], ah[tm][3], b0, b1);
                }
            }
        }
    }

    // ---- epilogue ----
    #pragma unroll
    for (int tm = 0; tm < 2; tm++) {
        const int r0 = bm + wm * 32 + tm * 16 + qr;
        #pragma unroll
        for (int tn = 0; tn < 8; tn++) {
            const int c0 = bn + wn * 64 + tn * 8 + 2 * qc;
            #pragma unroll
            for (int half = 0; half < 2; half++) {
                const int r = r0 + half * 8;
                float v0 = acc[tm][tn][half * 2 + 0];
                float v1 = acc[tm][tn][half * 2 + 1];
                if (bias && c0 < N) { v0 += bias[c0]; if (c0 + 1 < N) v1 += bias[c0 + 1]; }
                if (epi == 1) {
                    v0 = (v0 > 20.f) ? v0 : log1pf(expf(v0));
                    v1 = (v1 > 20.f) ? v1 : log1pf(expf(v1));
                }
                if (c0 + 1 < N) {
                    *(float2*)(C + (size_t)r * ldc + c0) = make_float2(v0, v1);
                } else if (c0 < N) {
                    C[(size_t)r * ldc + c0] = v0;
                }
            }
        }
    }
}

// ---------------- causal depthwise conv (K=4) + SiLU, float4 along d ------
__global__ __launch_bounds__(256)
void conv_silu_kernel(const float* __restrict__ conv_w, const float* __restrict__ conv_b)
{
    const size_t total4 = (size_t)BATCH * LSEQ * (DINNER / 4);
    size_t idx = (size_t)blockIdx.x * blockDim.x + threadIdx.x;
    if (idx >= total4) return;
    const int d4 = (int)(idx % (DINNER / 4));
    const int l  = (int)((idx / (DINNER / 4)) % LSEQ);
    const int b  = (int)(idx / ((size_t)(DINNER / 4) * LSEQ));
    const int d  = d4 * 4;

    float acc0 = conv_b[d], acc1 = conv_b[d + 1], acc2 = conv_b[d + 2], acc3 = conv_b[d + 3];
    #pragma unroll
    for (int k = 0; k < 4; k++) {
        const int ls = l - 3 + k;
        if (ls >= 0) {
            const float4 v = *(const float4*)(&g_xr[((size_t)b * LSEQ + ls) * (2 * DINNER) + d]);
            acc0 = fmaf(conv_w[(d + 0) * 4 + k], v.x, acc0);
            acc1 = fmaf(conv_w[(d + 1) * 4 + k], v.y, acc1);
            acc2 = fmaf(conv_w[(d + 2) * 4 + k], v.z, acc2);
            acc3 = fmaf(conv_w[(d + 3) * 4 + k], v.w, acc3);
        }
    }
    float4 o;
    o.x = acc0 / (1.f + __expf(-acc0));
    o.y = acc1 / (1.f + __expf(-acc1));
    o.z = acc2 / (1.f + __expf(-acc2));
    o.w = acc3 / (1.f + __expf(-acc3));
    *(float4*)(&g_xc[((size_t)b * LSEQ + l) * DINNER + d]) = o;
}

// ---------------- selective scan over L (+x*D, fused gate) --------------
#define SCAN_T 128
__global__ __launch_bounds__(64)
void scan_kernel(const float* __restrict__ A_log, const float* __restrict__ D_par)
{
    __shared__ float sBC[SCAN_T][32];

    const int tid = threadIdx.x;
    const int d = blockIdx.x * 64 + tid;
    const int b = blockIdx.y;

    float A[NST];
    #pragma unroll
    for (int n = 0; n < NST; n++) A[n] = -expf(A_log[d * NST + n]);
    float h[NST];
    #pragma unroll
    for (int n = 0; n < NST; n++) h[n] = 0.f;
    const float Dp = D_par[d];

    size_t pd = (size_t)b * LSEQ * DINNER + d;
    size_t pr = (size_t)b * LSEQ * (2 * DINNER) + DINNER + d;

    float dt_nx = g_dt[pd];
    float xt_nx = g_xc[pd];
    float rr_nx = g_xr[pr];

    const float* xdb = g_xdbl + (size_t)b * LSEQ * XDBLC + DTR;

    for (int c = 0; c < LSEQ / SCAN_T; c++) {
        __syncthreads();
        const float* src = xdb + (size_t)c * SCAN_T * XDBLC;
        #pragma unroll 4
        for (int i = tid; i < SCAN_T * 8; i += 64) {
            const int row = i >> 3, c4 = (i & 7) * 4;
            *(float4*)&sBC[row][c4] = *(const float4*)(src + (size_t)row * XDBLC + c4);
        }
        __syncthreads();

        for (int t = 0; t < SCAN_T; t++) {
            const float dt = dt_nx, xt = xt_nx, rr = rr_nx;
            const size_t pd_cur = pd;
            const int l = c * SCAN_T + t;
            pd += DINNER; pr += 2 * DINNER;
            if (l + 1 < LSEQ) {
                dt_nx = g_dt[pd];
                xt_nx = g_xc[pd];
                rr_nx = g_xr[pr];
            }
            const float dtx = dt * xt;
            float yt = 0.f;
            #pragma unroll
            for (int n = 0; n < NST; n++) {
                const float dA = __expf(dt * A[n]);
                h[n] = fmaf(h[n], dA, dtx * sBC[t][n]);
                yt   = fmaf(h[n], sBC[t][NST + n], yt);
            }
            const float gate = rr / (1.f + __expf(-rr));
            g_xc[pd_cur] = fmaf(xt, Dp, yt) * gate;
        }
    }
}

// ---------------- launch -------------------------------------------------
extern "C" void kernel_launch(void* const* d_in, const int* in_sizes, int n_in,
                              void* d_out, int out_size)
{
    const float* x      = (const float*)d_in[0];
    const float* W_in   = (const float*)d_in[1];
    const float* b_in   = (const float*)d_in[2];
    const float* conv_w = (const float*)d_in[3];
    const float* conv_b = (const float*)d_in[4];
    const float* W_x    = (const float*)d_in[5];
    const float* W_dt   = (const float*)d_in[6];
    const float* b_dt   = (const float*)d_in[7];
    const float* A_log  = (const float*)d_in[8];
    const float* D_par  = (const float*)d_in[9];
    const float* W_out  = (const float*)d_in[10];
    const float* b_out  = (const float*)d_in[11];
    float* out = (float*)d_out;

    float *xr, *xc, *xdbl, *dt;
    cudaGetSymbolAddress((void**)&xr,   g_xr);
    cudaGetSymbolAddress((void**)&xc,   g_xc);
    cudaGetSymbolAddress((void**)&xdbl, g_xdbl);
    cudaGetSymbolAddress((void**)&dt,   g_dt);

    cudaFuncSetAttribute(mma_gemm, cudaFuncAttributeMaxDynamicSharedMemorySize, SMEM_GEMM);

    const int M = BATCH * LSEQ;   // 16384

    // 1) in-projection: [M,1024] @ [1024,4096] -> g_xr
    mma_gemm<<<dim3((2 * DINNER) / 128, M / 128), 256, SMEM_GEMM>>>(
        x, W_in, b_in, xr, M, 2 * DINNER, DMODEL, DMODEL, 2 * DINNER, 2 * DINNER, 0);

    // 2) causal depthwise conv + silu -> g_xc
    {
        const size_t total4 = (size_t)M * (DINNER / 4);
        conv_silu_kernel<<<(unsigned)((total4 + 255) / 256), 256>>>(conv_w, conv_b);
    }

    // 3) x_dbl: [M,2048] @ [2048,96] -> g_xdbl
    mma_gemm<<<dim3(1, M / 128), 256, SMEM_GEMM>>>(
        xc, W_x, nullptr, xdbl, M, XDBLC, DINNER, DINNER, XDBLC, XDBLC, 0);

    // 4) delta: softplus([M,64] @ [64,2048] + b_dt) -> g_dt
    mma_gemm<<<dim3(DINNER / 128, M / 128), 256, SMEM_GEMM>>>(
        xdbl, W_dt, b_dt, dt, M, DINNER, DTR, XDBLC, DINNER, DINNER, 1);

    // 5) selective scan (y in place over g_xc, + x*D, * silu(res))
    scan_kernel<<<dim3(DINNER / 64, BATCH), 64>>>(A_log, D_par);

    // 6) out-projection: [M,2048] @ [2048,1024] + b_out -> d_out
    mma_gemm<<<dim3(DMODEL / 128, M / 128), 256, SMEM_GEMM>>>(
        xc, W_out, b_out, out, M, DMODEL, DINNER, DINNER, DMODEL, DMODEL, 0);
}

// round 10
// speedup vs baseline: 1.4465x; 1.3162x over previous
#include <cuda_runtime.h>
#include <math.h>
#include <stdint.h>

#define BATCH  4
#define LSEQ   4096
#define DMODEL 1024
#define DINNER 2048
#define DTR    64
#define NST    16
#define XDBLC  96   // dt_rank + 2*N

// ---------------- scratch (device globals) ----------------
__device__ float g_xr  [(size_t)BATCH * LSEQ * (2 * DINNER)];  // in-proj out (x | res)
__device__ float g_xc  [(size_t)BATCH * LSEQ * DINNER];        // conv+silu (tf32) -> y(gated,tf32) in place
__device__ float g_xdbl[(size_t)BATCH * LSEQ * XDBLC];         // tf32-rounded
__device__ float g_dt  [(size_t)BATCH * LSEQ * DINNER];        // full fp32 (scan-only)
__device__ float g_xt  [(size_t)BATCH * LSEQ * DMODEL];        // tf32-rounded x
__device__ float g_Win [(size_t)DMODEL * (2 * DINNER)];        // tf32-rounded weights
__device__ float g_Wx  [(size_t)DINNER * XDBLC];
__device__ float g_Wdt [(size_t)DTR * DINNER];
__device__ float g_Wout[(size_t)DINNER * DMODEL];

// ---------------- helpers ----------------
__device__ __forceinline__ uint32_t smem_u32(const void* p) {
    uint32_t a;
    asm("{ .reg .u64 t; cvta.to.shared.u64 t, %1; cvt.u32.u64 %0, t; }" : "=r"(a) : "l"(p));
    return a;
}
__device__ __forceinline__ float f2tf(float f) {
    uint32_t r; asm("cvt.rna.tf32.f32 %0, %1;" : "=r"(r) : "f"(f));
    return __uint_as_float(r);
}
__device__ __forceinline__ void cp16(uint32_t dst, const void* src, uint32_t sz) {
    asm volatile("cp.async.cg.shared.global [%0], [%1], 16, %2;"
                 :: "r"(dst), "l"(src), "r"(sz) : "memory");
}
__device__ __forceinline__ void mma8(float* c,
    uint32_t a0, uint32_t a1, uint32_t a2, uint32_t a3, uint32_t b0, uint32_t b1)
{
    asm volatile(
        "mma.sync.aligned.m16n8k8.row.col.f32.tf32.tf32.f32 "
        "{%0,%1,%2,%3}, {%4,%5,%6,%7}, {%8,%9}, {%0,%1,%2,%3};"
        : "+f"(c[0]), "+f"(c[1]), "+f"(c[2]), "+f"(c[3])
        : "r"(a0), "r"(a1), "r"(a2), "r"(a3), "r"(b0), "r"(b1));
}

// ---------------- smem layout: 3 stages, A [128][36], B [32][136] ----------
#define A_ST  18432                 // 128*36*4
#define B_ST  17408                 // 32*136*4
#define B_BASE (3 * A_ST)           // 55296
#define SMEM_GEMM (3 * A_ST + 3 * B_ST)   // 107520 -> 2 blocks/SM

// C[M,N] = A[M,K] @ B[K,N] (+bias). epi: 0=none, 1=softplus, 2=tf32-round output.
// Inputs A,B are pre-rounded tf32 values in fp32 storage -> pure 1xTF32 MMA.
// M % 128 == 0, K % 32 == 0; N mult of 2 (guarded).
__global__ __launch_bounds__(256, 2)
void mma_gemm(const float* __restrict__ A, const float* __restrict__ B,
              const float* __restrict__ bias, float* __restrict__ C,
              int M, int N, int K, int lda, int ldb, int ldc, int epi)
{
    extern __shared__ char smc[];
    const uint32_t sb = smem_u32(smc);
    const int tid = threadIdx.x;
    const int bm = blockIdx.y * 128;
    const int bn = blockIdx.x * 128;
    const int wid = tid >> 5, lane = tid & 31;
    const int wm = wid >> 1, wn = wid & 1;     // 4x2 warps, warp tile 32x64
    const int qr = lane >> 2, qc = lane & 3;

    float acc[2][8][4];
    #pragma unroll
    for (int i = 0; i < 2; i++)
        #pragma unroll
        for (int j = 0; j < 8; j++)
            #pragma unroll
            for (int e = 0; e < 4; e++) acc[i][j][e] = 0.f;

    const int rA = tid >> 3, cA = (tid & 7) * 4;     // A loader: +32 rows per t
    const int kB = tid >> 5, nB = (tid & 31) * 4;    // B loader: +8 rows per t
    const uint32_t bsz = (bn + nB < N) ? 16u : 0u;
    const int nclamp = (bn + nB < N) ? (bn + nB) : 0;

    const int nch = K >> 5;

    auto issue = [&](int ch) {
        const int kt = ch << 5;
        const int st = ch - (ch / 3) * 3;
        const uint32_t dA = sb + st * A_ST;
        const uint32_t dB = sb + B_BASE + st * B_ST;
        #pragma unroll
        for (int t = 0; t < 4; t++) {
            const int r = rA + t * 32;
            cp16(dA + (uint32_t)(r * 36 + cA) * 4,
                 A + (size_t)(bm + r) * lda + kt + cA, 16u);
            const int k = kB + t * 8;
            cp16(dB + (uint32_t)(k * 136 + nB) * 4,
                 B + (size_t)(kt + k) * ldb + nclamp, bsz);
        }
        asm volatile("cp.async.commit_group;" ::: "memory");
    };

    issue(0);
    issue(1);   // nch >= 2 always (K >= 64)

    for (int i = 0; i < nch; i++) {
        if (i + 1 < nch) { asm volatile("cp.async.wait_group 1;" ::: "memory"); }
        else             { asm volatile("cp.async.wait_group 0;" ::: "memory"); }
        __syncthreads();                 // stage i visible; compute(i-1) done everywhere
        if (i + 2 < nch) issue(i + 2);   // reuses stage (i-1)%3 — safe after barrier

        const int st = i - (i / 3) * 3;
        const uint32_t* Ahi = (const uint32_t*)(smc + st * A_ST);
        const uint32_t* Bsm = (const uint32_t*)(smc + B_BASE + st * B_ST);

        #pragma unroll
        for (int kk = 0; kk < 32; kk += 8) {
            uint32_t ah[2][4];
            #pragma unroll
            for (int tm = 0; tm < 2; tm++) {
                const int r0 = wm * 32 + tm * 16 + qr;
                ah[tm][0] = Ahi[r0 * 36 + kk + qc];
                ah[tm][1] = Ahi[(r0 + 8) * 36 + kk + qc];
                ah[tm][2] = Ahi[r0 * 36 + kk + qc + 4];
                ah[tm][3] = Ahi[(r0 + 8) * 36 + kk + qc + 4];
            }
            #pragma unroll
            for (int tn = 0; tn < 8; tn++) {
                const int col = wn * 64 + tn * 8 + qr;
                const uint32_t b0 = Bsm[(kk + qc) * 136 + col];
                const uint32_t b1 = Bsm[(kk + qc + 4) * 136 + col];
                #pragma unroll
                for (int tm = 0; tm < 2; tm++)
                    mma8(acc[tm][tn], ah[tm][0], ah[tm][1], ah[tm][2], ah[tm][3], b0, b1);
            }
        }
    }

    // ---- epilogue ----
    #pragma unroll
    for (int tm = 0; tm < 2; tm++) {
        const int r0 = bm + wm * 32 + tm * 16 + qr;
        #pragma unroll
        for (int tn = 0; tn < 8; tn++) {
            const int c0 = bn + wn * 64 + tn * 8 + 2 * qc;
            #pragma unroll
            for (int half = 0; half < 2; half++) {
                const int r = r0 + half * 8;
                float v0 = acc[tm][tn][half * 2 + 0];
                float v1 = acc[tm][tn][half * 2 + 1];
                if (bias && c0 < N) { v0 += bias[c0]; if (c0 + 1 < N) v1 += bias[c0 + 1]; }
                if (epi == 1) {
                    v0 = (v0 > 20.f) ? v0 : log1pf(expf(v0));
                    v1 = (v1 > 20.f) ? v1 : log1pf(expf(v1));
                } else if (epi == 2) {
                    v0 = f2tf(v0); v1 = f2tf(v1);
                }
                if (c0 + 1 < N) {
                    *(float2*)(C + (size_t)r * ldc + c0) = make_float2(v0, v1);
                } else if (c0 < N) {
                    C[(size_t)r * ldc + c0] = v0;
                }
            }
        }
    }
}

// ---------------- round-copy: dst = tf32_rna(src), float4 ----------------
__global__ __launch_bounds__(256)
void round_copy(const float* __restrict__ src, float* __restrict__ dst, size_t n4)
{
    size_t i = (size_t)blockIdx.x * blockDim.x + threadIdx.x;
    if (i >= n4) return;
    const float4 v = ((const float4*)src)[i];
    float4 o;
    o.x = f2tf(v.x); o.y = f2tf(v.y); o.z = f2tf(v.z); o.w = f2tf(v.w);
    ((float4*)dst)[i] = o;
}

// ---------------- causal depthwise conv (K=4) + SiLU -> tf32 --------------
__global__ __launch_bounds__(256)
void conv_silu_kernel(const float* __restrict__ conv_w, const float* __restrict__ conv_b)
{
    const size_t total4 = (size_t)BATCH * LSEQ * (DINNER / 4);
    size_t idx = (size_t)blockIdx.x * blockDim.x + threadIdx.x;
    if (idx >= total4) return;
    const int d4 = (int)(idx % (DINNER / 4));
    const int l  = (int)((idx / (DINNER / 4)) % LSEQ);
    const int b  = (int)(idx / ((size_t)(DINNER / 4) * LSEQ));
    const int d  = d4 * 4;

    float acc0 = conv_b[d], acc1 = conv_b[d + 1], acc2 = conv_b[d + 2], acc3 = conv_b[d + 3];
    #pragma unroll
    for (int k = 0; k < 4; k++) {
        const int ls = l - 3 + k;
        if (ls >= 0) {
            const float4 v = *(const float4*)(&g_xr[((size_t)b * LSEQ + ls) * (2 * DINNER) + d]);
            acc0 = fmaf(conv_w[(d + 0) * 4 + k], v.x, acc0);
            acc1 = fmaf(conv_w[(d + 1) * 4 + k], v.y, acc1);
            acc2 = fmaf(conv_w[(d + 2) * 4 + k], v.z, acc2);
            acc3 = fmaf(conv_w[(d + 3) * 4 + k], v.w, acc3);
        }
    }
    float4 o;
    o.x = f2tf(acc0 / (1.f + __expf(-acc0)));
    o.y = f2tf(acc1 / (1.f + __expf(-acc1)));
    o.z = f2tf(acc2 / (1.f + __expf(-acc2)));
    o.w = f2tf(acc3 / (1.f + __expf(-acc3)));
    *(float4*)(&g_xc[((size_t)b * LSEQ + l) * DINNER + d]) = o;
}

// ---------------- selective scan over L (+x*D, fused gate) --------------
#define SCAN_T 128
__global__ __launch_bounds__(64)
void scan_kernel(const float* __restrict__ A_log, const float* __restrict__ D_par)
{
    __shared__ float sBC[SCAN_T][32];

    const int tid = threadIdx.x;
    const int d = blockIdx.x * 64 + tid;
    const int b = blockIdx.y;

    float A[NST];
    #pragma unroll
    for (int n = 0; n < NST; n++) A[n] = -expf(A_log[d * NST + n]);
    // structural fast path: A[n] == (n+1)*A[0]  (true for A_log = log(1..16))
    bool fast = true;
    #pragma unroll
    for (int n = 0; n < NST; n++)
        fast = fast && (fabsf(A[n] - (float)(n + 1) * A[0]) <= 1e-4f * (float)(n + 1));

    float h[NST];
    #pragma unroll
    for (int n = 0; n < NST; n++) h[n] = 0.f;
    const float Dp = D_par[d];

    size_t pd = (size_t)b * LSEQ * DINNER + d;
    size_t pr = (size_t)b * LSEQ * (2 * DINNER) + DINNER + d;

    float dt_nx = g_dt[pd];
    float xt_nx = g_xc[pd];
    float rr_nx = g_xr[pr];

    const float* xdb = g_xdbl + (size_t)b * LSEQ * XDBLC + DTR;

    for (int c = 0; c < LSEQ / SCAN_T; c++) {
        __syncthreads();
        const float* src = xdb + (size_t)c * SCAN_T * XDBLC;
        #pragma unroll 4
        for (int i = tid; i < SCAN_T * 8; i += 64) {
            const int row = i >> 3, c4 = (i & 7) * 4;
            *(float4*)&sBC[row][c4] = *(const float4*)(src + (size_t)row * XDBLC + c4);
        }
        __syncthreads();

        for (int t = 0; t < SCAN_T; t++) {
            const float dt = dt_nx, xt = xt_nx, rr = rr_nx;
            const size_t pd_cur = pd;
            const int l = c * SCAN_T + t;
            pd += DINNER; pr += 2 * DINNER;
            if (l + 1 < LSEQ) {
                dt_nx = g_dt[pd];
                xt_nx = g_xc[pd];
                rr_nx = g_xr[pr];
            }
            float dA[NST];
            if (fast) {
                const float e1 = __expf(dt * A[0]);
                const float e2 = e1 * e1, e3 = e2 * e1, e4 = e2 * e2;
                const float e5 = e4 * e1, e6 = e4 * e2, e7 = e4 * e3, e8 = e4 * e4;
                dA[0] = e1;  dA[1] = e2;  dA[2] = e3;  dA[3] = e4;
                dA[4] = e5;  dA[5] = e6;  dA[6] = e7;  dA[7] = e8;
                dA[8]  = e8 * e1;  dA[9]  = e8 * e2;  dA[10] = e8 * e3;  dA[11] = e8 * e4;
                dA[12] = e8 * e5;  dA[13] = e8 * e6;  dA[14] = e8 * e7;  dA[15] = e8 * e8;
            } else {
                #pragma unroll
                for (int n = 0; n < NST; n++) dA[n] = __expf(dt * A[n]);
            }
            const float dtx = dt * xt;
            float y0 = 0.f, y1 = 0.f, y2 = 0.f, y3 = 0.f;
            #pragma unroll
            for (int n = 0; n < NST; n += 4) {
                h[n + 0] = fmaf(h[n + 0], dA[n + 0], dtx * sBC[t][n + 0]);
                h[n + 1] = fmaf(h[n + 1], dA[n + 1], dtx * sBC[t][n + 1]);
                h[n + 2] = fmaf(h[n + 2], dA[n + 2], dtx * sBC[t][n + 2]);
                h[n + 3] = fmaf(h[n + 3], dA[n + 3], dtx * sBC[t][n + 3]);
                y0 = fmaf(h[n + 0], sBC[t][NST + n + 0], y0);
                y1 = fmaf(h[n + 1], sBC[t][NST + n + 1], y1);
                y2 = fmaf(h[n + 2], sBC[t][NST + n + 2], y2);
                y3 = fmaf(h[n + 3], sBC[t][NST + n + 3], y3);
            }
            const float yt = (y0 + y1) + (y2 + y3);
            const float gate = rr / (1.f + __expf(-rr));
            g_xc[pd_cur] = f2tf(fmaf(xt, Dp, yt) * gate);   // tf32 for out-proj A
        }
    }
}

// ---------------- launch -------------------------------------------------
extern "C" void kernel_launch(void* const* d_in, const int* in_sizes, int n_in,
                              void* d_out, int out_size)
{
    const float* x      = (const float*)d_in[0];
    const float* W_in   = (const float*)d_in[1];
    const float* b_in   = (const float*)d_in[2];
    const float* conv_w = (const float*)d_in[3];
    const float* conv_b = (const float*)d_in[4];
    const float* W_x    = (const float*)d_in[5];
    const float* W_dt   = (const float*)d_in[6];
    const float* b_dt   = (const float*)d_in[7];
    const float* A_log  = (const float*)d_in[8];
    const float* D_par  = (const float*)d_in[9];
    const float* W_out  = (const float*)d_in[10];
    const float* b_out  = (const float*)d_in[11];
    float* out = (float*)d_out;

    float *xr, *xc, *xdbl, *dt, *xt, *Win, *Wx, *Wdt, *Wout;
    cudaGetSymbolAddress((void**)&xr,   g_xr);
    cudaGetSymbolAddress((void**)&xc,   g_xc);
    cudaGetSymbolAddress((void**)&xdbl, g_xdbl);
    cudaGetSymbolAddress((void**)&dt,   g_dt);
    cudaGetSymbolAddress((void**)&xt,   g_xt);
    cudaGetSymbolAddress((void**)&Win,  g_Win);
    cudaGetSymbolAddress((void**)&Wx,   g_Wx);
    cudaGetSymbolAddress((void**)&Wdt,  g_Wdt);
    cudaGetSymbolAddress((void**)&Wout, g_Wout);

    cudaFuncSetAttribute(mma_gemm, cudaFuncAttributeMaxDynamicSharedMemorySize, SMEM_GEMM);

    const int M = BATCH * LSEQ;   // 16384

    // 0) pre-round all GEMM operands to tf32
    auto rc = [](const float* s, float* d, size_t n) {
        const size_t n4 = n / 4;
        round_copy<<<(unsigned)((n4 + 255) / 256), 256>>>(s, d, n4);
    };
    rc(x,     xt,   (size_t)M * DMODEL);
    rc(W_in,  Win,  (size_t)DMODEL * 2 * DINNER);
    rc(W_x,   Wx,   (size_t)DINNER * XDBLC);
    rc(W_dt,  Wdt,  (size_t)DTR * DINNER);
    rc(W_out, Wout, (size_t)DINNER * DMODEL);

    // 1) in-projection: [M,1024] @ [1024,4096] -> g_xr (full fp32 out)
    mma_gemm<<<dim3((2 * DINNER) / 128, M / 128), 256, SMEM_GEMM>>>(
        xt, Win, b_in, xr, M, 2 * DINNER, DMODEL, DMODEL, 2 * DINNER, 2 * DINNER, 0);

    // 2) causal depthwise conv + silu -> g_xc (tf32)
    {
        const size_t total4 = (size_t)M * (DINNER / 4);
        conv_silu_kernel<<<(unsigned)((total4 + 255) / 256), 256>>>(conv_w, conv_b);
    }

    // 3) x_dbl: [M,2048] @ [2048,96] -> g_xdbl (tf32 out, epi=2)
    mma_gemm<<<dim3(1, M / 128), 256, SMEM_GEMM>>>(
        xc, Wx, nullptr, xdbl, M, XDBLC, DINNER, DINNER, XDBLC, XDBLC, 2);

    // 4) delta: softplus([M,64] @ [64,2048] + b_dt) -> g_dt (full fp32)
    mma_gemm<<<dim3(DINNER / 128, M / 128), 256, SMEM_GEMM>>>(
        xdbl, Wdt, b_dt, dt, M, DINNER, DTR, XDBLC, DINNER, DINNER, 1);

    // 5) selective scan (y in place over g_xc, + x*D, * silu(res), tf32 out)
    scan_kernel<<<dim3(DINNER / 64, BATCH), 64>>>(A_log, D_par);

    // 6) out-projection: [M,2048] @ [2048,1024] + b_out -> d_out
    mma_gemm<<<dim3(DMODEL / 128, M / 128), 256, SMEM_GEMM>>>(
        xc, Wout, b_out, out, M, DMODEL, DINNER, DINNER, DMODEL, DMODEL, 0);
}